// round 13
// baseline (speedup 1.0000x reference)
#include <cuda_runtime.h>

// Problem constants (from reference: B=2048, N=60, C=128)
#define BCOL 2048
#define NL   60
#define CCH  128
#define BLOCK 64          // threads per block; each thread owns 2 channels
#define LSTR 64           // layer stride in float2 units (CCH/2)

// dynamic smem: ONE per-thread float2 array of NL entries, [layer][thread].
// rs[] (phase A), overwritten by rt[] (phase B). 30720 B -> 7 blocks/SM.
#define SMEM_BYTES (NL * BLOCK * sizeof(float2))

// ---- float2 componentwise helpers (math identical per component) ----
__device__ __forceinline__ float2 operator*(float2 a, float2 b) {
    return make_float2(a.x * b.x, a.y * b.y);
}
__device__ __forceinline__ float2 operator+(float2 a, float2 b) {
    return make_float2(a.x + b.x, a.y + b.y);
}
__device__ __forceinline__ float2 frcp2(float2 v) {
    return make_float2(__fdividef(1.0f, v.x), __fdividef(1.0f, v.y));
}
__device__ __forceinline__ float2 onesub(float2 a, float2 b) {   // 1 - a*b
    return make_float2(1.0f - a.x * b.x, 1.0f - a.y * b.y);
}
__device__ __forceinline__ float2 onepl(float2 a, float2 b) {    // 1 + a*b
    return make_float2(1.0f + a.x * b.x, 1.0f + a.y * b.y);
}

struct BufA { float2 rv[4], tv[4]; };
struct BufB { float2 sv[4], rv[4], tv[4], av[4]; };
struct BufC { float2 sv[4], rv[4], tv[4], av[4], abv[4]; };

struct BState { float2 s_prev, r_prev, ds_prev, rt_run, F; };
struct CState { float2 Fu, s_m, r_m, dt_m; };

// ---- load helpers: batch loads back-to-back, LDG.64 each ----
__device__ __forceinline__ void loadA(BufA& B, const float2* __restrict__ r,
                                      const float2* __restrict__ t,
                                      unsigned base, int l0) {
    #pragma unroll
    for (int k = 0; k < 4; ++k) {
        unsigned idx = base + (unsigned)(l0 - k) * LSTR;
        B.rv[k] = r[idx];
        B.tv[k] = t[idx];
    }
}
__device__ __forceinline__ void loadB(BufB& B, const float2* __restrict__ s,
                                      const float2* __restrict__ r,
                                      const float2* __restrict__ t,
                                      const float2* __restrict__ a,
                                      unsigned base, int l0) {
    #pragma unroll
    for (int k = 0; k < 4; ++k) {
        unsigned idx = base + (unsigned)(l0 + k) * LSTR;
        B.sv[k] = s[idx];
        B.rv[k] = r[idx];
        B.tv[k] = t[idx];
        B.av[k] = a[idx];
    }
}
// pure-input part of a phase-C batch: SAFE to hoist before phase-B writes
__device__ __forceinline__ void loadCin(BufC& B, const float2* __restrict__ s,
                                        const float2* __restrict__ r,
                                        const float2* __restrict__ t,
                                        const float2* __restrict__ a,
                                        unsigned base, int m0) {
    #pragma unroll
    for (int k = 0; k < 4; ++k) {
        unsigned idx = base + (unsigned)(m0 - 1 - k) * LSTR;
        B.sv[k]  = __ldcs(&s[idx]);   // last use of inputs
        B.rv[k]  = __ldcs(&r[idx]);
        B.tv[k]  = __ldcs(&t[idx]);
        B.av[k]  = __ldcs(&a[idx]);
    }
}
// absorbed_down part: MUST issue after phase B wrote ab for these layers
__device__ __forceinline__ void loadCab(BufC& B, const float2* __restrict__ ab,
                                        unsigned base, int m0) {
    #pragma unroll
    for (int k = 0; k < 4; ++k) {
        unsigned idx = base + (unsigned)(m0 - 1 - k) * LSTR;
        B.abv[k] = __ldcs(&ab[idx]);  // read once, then overwritten
    }
}
__device__ __forceinline__ void loadC(BufC& B, const float2* __restrict__ s,
                                      const float2* __restrict__ r,
                                      const float2* __restrict__ t,
                                      const float2* __restrict__ a,
                                      const float2* __restrict__ ab,
                                      unsigned base, int m0) {
    loadCin(B, s, r, t, a, base, m0);
    loadCab(B, ab, base, m0);
}

// ---- compute helpers (per-component math identical to R12) ----
__device__ __forceinline__ float2 compA(float2 rs_run, const BufA& B, int l0,
                                        float2* sh, int tx) {
    #pragma unroll
    for (int k = 0; k < 4; ++k) {
        float2 dd = frcp2(onesub(rs_run, B.rv[k]));
        rs_run = B.rv[k] + rs_run * B.tv[k] * B.tv[k] * dd;
        sh[(l0 - k) * BLOCK + tx] = rs_run;
    }
    return rs_run;
}

// Phase B with fused reciprocal: x = 1/(p*q); ds = x*q; dt = x*p
__device__ __forceinline__ void compB(BState& st, const BufB& Bu, int l0,
                                      float2* sh, int tx, unsigned base,
                                      float2* fd, float2* ab) {
    float2 rsv[4];
    #pragma unroll
    for (int k = 0; k < 4; ++k)
        rsv[k] = sh[(l0 + k + 1) * BLOCK + tx];   // rs[l+1]
    #pragma unroll
    for (int k = 0; k < 4; ++k) {
        unsigned idx = base + (unsigned)(l0 + k) * LSTR;
        float2 s_down = st.ds_prev * (st.s_prev + Bu.sv[k] * st.r_prev);
        float2 G = st.F + s_down;
        __stcs(&fd[idx], G);

        float2 p = onesub(rsv[k], Bu.rv[k]);      // ds denominator
        float2 q = onesub(st.rt_run, Bu.rv[k]);   // dt denominator
        float2 x = frcp2(p * q);
        float2 dsl = x * q;                        // ds[l]
        float2 dtl = x * p;                        // dt[l]

        float2 td = Bu.tv[k] * dsl;
        ab[idx] = Bu.av[k] * onepl(rsv[k], td) * G;   // re-read in C
        st.F = G * td;
        st.ds_prev = dsl;

        st.rt_run = Bu.rv[k] + st.rt_run * Bu.tv[k] * Bu.tv[k] * dtl;
        sh[(l0 + k) * BLOCK + tx] = st.rt_run;        // overwrite dead rs

        st.s_prev = Bu.sv[k];
        st.r_prev = Bu.rv[k];
    }
}

// Phase C with pairwise-fused reciprocals (per component)
__device__ __forceinline__ void compC(CState& st, const BufC& Bu, int m0,
                                      float2* sh, int tx, unsigned base,
                                      float2* fu, float2* ab) {
    float2 rtv[4], qv[4], dtv[4];
    #pragma unroll
    for (int k = 0; k < 4; ++k)
        rtv[k] = sh[(m0 - 2 - k) * BLOCK + tx];   // rt[m-2]
    #pragma unroll
    for (int k = 0; k < 4; ++k)
        qv[k] = onesub(rtv[k], Bu.rv[k]);
    {
        float2 x01 = frcp2(qv[0] * qv[1]);
        float2 x23 = frcp2(qv[2] * qv[3]);
        dtv[0] = x01 * qv[1];
        dtv[1] = x01 * qv[0];
        dtv[2] = x23 * qv[3];
        dtv[3] = x23 * qv[2];
    }
    #pragma unroll
    for (int k = 0; k < 4; ++k) {
        int mm = m0 - k;
        float2 dt_m1 = dtv[k];                          // dt[mm-1]
        float2 s_up = st.dt_m * (st.s_m + Bu.sv[k] * st.r_m);
        float2 G = st.Fu + s_up;
        __stcs(&fu[base + (unsigned)mm * LSTR], G);

        float2 tdm1 = Bu.tv[k] * dt_m1;
        float2 au = G * Bu.av[k] * onepl(rtv[k], tdm1);
        __stcs(&ab[base + (unsigned)(mm - 1) * LSTR], Bu.abv[k] + au);
        st.Fu = G * tdm1;

        st.s_m = Bu.sv[k];
        st.r_m = Bu.rv[k];
        st.dt_m = dt_m1;
    }
}

__global__ __launch_bounds__(BLOCK, 7)   // 7 blocks/SM, reg cap 146
void adding_doubling_kernel(const float2* __restrict__ a,
                            const float2* __restrict__ r,
                            const float2* __restrict__ t,
                            const float2* __restrict__ s,
                            float2* __restrict__ out)
{
    extern __shared__ float2 smem[];
    const int tx = threadIdx.x;

    const unsigned tid = blockIdx.x * BLOCK + tx;      // float2-pair id
    const unsigned b = tid >> 6;                       // column
    const unsigned c = tid & 63;                       // channel pair
    const unsigned base = b * (NL * LSTR) + c;         // float2 units
    const unsigned BNC  = (unsigned)BCOL * NL * LSTR;  // float2 units

    float2* fd = out;            // flux_down
    float2* fu = out + BNC;      // flux_up
    float2* ab = out + 2u * BNC; // absorbed

#define SH_R(l) smem[(l) * BLOCK + tx]

    BufB B0, B1;   // phase-B buffers (B0 pre-loaded during phase A tail)

    // ---------------- Phase A: bottom-up cumulative surface reflection ----
    // ROLLED pipeline: batches l0 = 58,54,...,6 (l=58..3), tail l=2,1
    {
        float2 rs_run = r[base + (NL - 1) * LSTR];
        SH_R(NL - 1) = rs_run;

        BufA A0, A1;
        int l = NL - 2;                       // 58
        loadA(A0, r, t, base, l);
        #pragma unroll 1
        for (int it = 0; it < 6; ++it, l -= 8) {
            loadA(A1, r, t, base, l - 4);
            rs_run = compA(rs_run, A0, l, smem, tx);
            loadA(A0, r, t, base, l - 8);
            rs_run = compA(rs_run, A1, l - 4, smem, tx);
        }
        // l == 10; A0 holds batch 10
        loadA(A1, r, t, base, 6);
        rs_run = compA(rs_run, A0, 10, smem, tx);
        loadB(B0, s, r, t, a, base, 1);       // hide phase-B cold start
        rs_run = compA(rs_run, A1, 6, smem, tx);

        #pragma unroll
        for (int l2 = 2; l2 >= 1; --l2) {     // tail
            unsigned idx = base + (unsigned)l2 * LSTR;
            float2 rl = r[idx], tl = t[idx];
            float2 dd = frcp2(onesub(rs_run, rl));
            rs_run = rl + rs_run * tl * tl * dd;
            SH_R(l2) = rs_run;
        }
    }

    BufC C0, C1;   // phase-C buffers (C0 inputs pre-loaded in phase B tail)

    // ---------------- Phase B: forward — down flux + top-down rt ----------
    // ROLLED pipeline: batches l0 = 1,5,...,53 (l=1..56), tail l=57..59
    {
        BState st;
        st.s_prev = s[base];
        st.r_prev = r[base];
        float2 rs1 = SH_R(1);
        st.ds_prev = frcp2(onesub(rs1, st.r_prev));   // ds[0]
        st.rt_run = st.r_prev;                         // rt[0]
        SH_R(0) = st.rt_run;
        __stcs(&fd[base], make_float2(0.0f, 0.0f));
        st.F = make_float2(0.0f, 0.0f);

        int l = 1;
        #pragma unroll 1
        for (int it = 0; it < 6; ++it, l += 8) {
            loadB(B1, s, r, t, a, base, l + 4);
            compB(st, B0, l, smem, tx, base, fd, ab);
            loadB(B0, s, r, t, a, base, l + 8);
            compB(st, B1, l + 4, smem, tx, base, fd, ab);
        }
        // l == 49; B0 holds batch 49
        loadB(B1, s, r, t, a, base, 53);
        compB(st, B0, 49, smem, tx, base, fd, ab);
        loadCin(C0, s, r, t, a, base, 59);    // SAFE hoist: pure inputs only
        compB(st, B1, 53, smem, tx, base, fd, ab);

        #pragma unroll
        for (int l2 = 57; l2 < NL; ++l2) {    // tail l = 57, 58, 59
            unsigned idx = base + (unsigned)l2 * LSTR;
            float2 sl = s[idx], rl = r[idx], tl = t[idx], al = a[idx];

            float2 s_down = st.ds_prev * (st.s_prev + sl * st.r_prev);
            float2 G = st.F + s_down;
            __stcs(&fd[idx], G);

            float2 absd;
            if (l2 < NL - 1) {
                float2 rsl1 = SH_R(l2 + 1);
                float2 dsl  = frcp2(onesub(rsl1, rl));
                float2 td = tl * dsl;
                absd = al * onepl(rsl1, td) * G;
                st.F = G * td;
                st.ds_prev = dsl;
            } else {
                absd = al * G;
            }
            ab[idx] = absd;

            float2 dd = frcp2(onesub(st.rt_run, rl));
            st.rt_run = rl + st.rt_run * tl * tl * dd;
            SH_R(l2) = st.rt_run;

            st.s_prev = sl;
            st.r_prev = rl;
        }
    }

    // ---------------- Phase C: reverse — up flux ---------------------------
    // ROLLED pipeline: batches m0 = 59,55,...,7 (m=59..4), tail m=3,2, epi.
    {
        // ab[55..58] were written by this same thread in phase B above;
        // load here (after the writes) — program-order correct, L1/L2 hit.
        loadCab(C0, ab, base, 59);

        CState st;
        st.Fu = make_float2(0.0f, 0.0f);
        unsigned idxN = base + (NL - 1) * LSTR;
        st.s_m = __ldcs(&s[idxN]);
        st.r_m = __ldcs(&r[idxN]);
        st.dt_m = frcp2(onesub(SH_R(NL - 2), st.r_m));   // dt[N-1]

        int m = NL - 1;                        // 59
        #pragma unroll 1
        for (int it = 0; it < 6; ++it, m -= 8) {
            loadC(C1, s, r, t, a, ab, base, m - 4);
            compC(st, C0, m, smem, tx, base, fu, ab);
            loadC(C0, s, r, t, a, ab, base, m - 8);
            compC(st, C1, m - 4, smem, tx, base, fu, ab);
        }
        // m == 11; C0 holds batch 11
        loadC(C1, s, r, t, a, ab, base, 7);
        compC(st, C0, 11, smem, tx, base, fu, ab);
        compC(st, C1, 7, smem, tx, base, fu, ab);

        #pragma unroll
        for (int m2 = 3; m2 >= 2; --m2) {      // tail m = 3, 2
            unsigned idxm1 = base + (unsigned)(m2 - 1) * LSTR;
            float2 s_m1 = __ldcs(&s[idxm1]);
            float2 r_m1 = __ldcs(&r[idxm1]);
            float2 t_m1 = __ldcs(&t[idxm1]);
            float2 a_m1 = __ldcs(&a[idxm1]);
            float2 ab_old = __ldcs(&ab[idxm1]);

            float2 rt_m2 = SH_R(m2 - 2);
            float2 dt_m1 = frcp2(onesub(rt_m2, r_m1));

            float2 s_up_m = st.dt_m * (st.s_m + s_m1 * st.r_m);
            float2 G = st.Fu + s_up_m;
            __stcs(&fu[base + (unsigned)m2 * LSTR], G);

            float2 tdm1 = t_m1 * dt_m1;
            float2 au = G * a_m1 * onepl(rt_m2, tdm1);
            __stcs(&ab[idxm1], ab_old + au);
            st.Fu = G * tdm1;

            st.s_m = s_m1;
            st.r_m = r_m1;
            st.dt_m = dt_m1;
        }

        // m = 1 and m = 0 epilogue; state: s_m=s[1], r_m=r[1], dt_m=dt[1]
        float2 s0 = __ldcs(&s[base]);
        float2 t0 = __ldcs(&t[base]);
        float2 a0 = __ldcs(&a[base]);
        float2 s_up1 = st.dt_m * (st.s_m + s0 * st.r_m);
        float2 flux1 = st.Fu + s_up1;
        __stcs(&fu[base + LSTR], flux1);          // flux_up[1]
        __stcs(&ab[base], flux1 * a0);            // absorbed[0] (down = 0)
        __stcs(&fu[base], flux1 * t0 + s0);       // flux_up[0]
    }

#undef SH_R
}

extern "C" void kernel_launch(void* const* d_in, const int* in_sizes, int n_in,
                              void* d_out, int out_size)
{
    const float2* a = (const float2*)d_in[0];
    const float2* r = (const float2*)d_in[1];
    const float2* t = (const float2*)d_in[2];
    const float2* s = (const float2*)d_in[3];
    float2* out = (float2*)d_out;

    cudaFuncSetAttribute(adding_doubling_kernel,
                         cudaFuncAttributeMaxDynamicSharedMemorySize,
                         (int)SMEM_BYTES);

    const int totalPairs = BCOL * CCH / 2;            // 131072
    const int grid = totalPairs / BLOCK;              // 2048 blocks
    adding_doubling_kernel<<<grid, BLOCK, SMEM_BYTES>>>(a, r, t, s, out);
}

// round 14
// speedup vs baseline: 1.0815x; 1.0815x over previous
#include <cuda_runtime.h>

// Problem constants (from reference: B=2048, N=60, C=128)
#define BCOL 2048
#define NL   60
#define CCH  128
#define BLOCK 64          // half-slab blocks: 64 channels per block

// dynamic smem: ONE per-thread array of NL floats, [layer][thread].
// 15 KB used, padded to 22 KB to cap residency at 10 blocks/SM
// (10 x 148 half-slabs x ~77 KB ~= 114 MB < 126 MB L2).
#define SMEM_BYTES  (22 * 1024)

__device__ __forceinline__ float frcp(float x) {
    return __fdividef(1.0f, x);     // MUFU.RCP path, ~2ulp
}

struct BufA { float rv[4], tv[4]; };
struct BufB { float sv[4], rv[4], tv[4], av[4]; };
struct BufC { float sv[4], rv[4], tv[4], av[4], abv[4]; };

struct BState { float s_prev, r_prev, ds_prev, rt_run, F; };
struct CState { float Fu, s_m, r_m, dt_m; };

// ---- load helpers: issue all batch loads back-to-back (max MLP) ----
__device__ __forceinline__ void loadA(BufA& B, const float* __restrict__ r,
                                      const float* __restrict__ t,
                                      unsigned base, int l0) {
    #pragma unroll
    for (int k = 0; k < 4; ++k) {
        unsigned idx = base + (unsigned)(l0 - k) * CCH;
        B.rv[k] = r[idx];
        B.tv[k] = t[idx];
    }
}
__device__ __forceinline__ void loadB(BufB& B, const float* __restrict__ s,
                                      const float* __restrict__ r,
                                      const float* __restrict__ t,
                                      const float* __restrict__ a,
                                      unsigned base, int l0) {
    #pragma unroll
    for (int k = 0; k < 4; ++k) {
        unsigned idx = base + (unsigned)(l0 + k) * CCH;
        B.sv[k] = s[idx];
        B.rv[k] = r[idx];
        B.tv[k] = t[idx];
        B.av[k] = a[idx];
    }
}
// pure-input part of a phase-C batch: SAFE to hoist before phase-B writes
__device__ __forceinline__ void loadCin(BufC& B, const float* __restrict__ s,
                                        const float* __restrict__ r,
                                        const float* __restrict__ t,
                                        const float* __restrict__ a,
                                        unsigned base, int m0) {
    #pragma unroll
    for (int k = 0; k < 4; ++k) {
        unsigned idx = base + (unsigned)(m0 - 1 - k) * CCH;
        B.sv[k]  = __ldcs(&s[idx]);   // last use of inputs
        B.rv[k]  = __ldcs(&r[idx]);
        B.tv[k]  = __ldcs(&t[idx]);
        B.av[k]  = __ldcs(&a[idx]);
    }
}
// absorbed_down part: MUST issue after phase B wrote ab for these layers
__device__ __forceinline__ void loadCab(BufC& B, const float* __restrict__ ab,
                                        unsigned base, int m0) {
    #pragma unroll
    for (int k = 0; k < 4; ++k) {
        unsigned idx = base + (unsigned)(m0 - 1 - k) * CCH;
        B.abv[k] = __ldcs(&ab[idx]);  // read once, then overwritten
    }
}
__device__ __forceinline__ void loadC(BufC& B, const float* __restrict__ s,
                                      const float* __restrict__ r,
                                      const float* __restrict__ t,
                                      const float* __restrict__ a,
                                      const float* __restrict__ ab,
                                      unsigned base, int m0) {
    loadCin(B, s, r, t, a, base, m0);
    loadCab(B, ab, base, m0);
}

// ---- compute helpers (math identical to R12) ----
__device__ __forceinline__ float compA(float rs_run, const BufA& B, int l0,
                                       float* sh, int tx) {
    #pragma unroll
    for (int k = 0; k < 4; ++k) {
        float dd = frcp(1.0f - rs_run * B.rv[k]);
        rs_run = B.rv[k] + rs_run * B.tv[k] * B.tv[k] * dd;
        sh[(l0 - k) * BLOCK + tx] = rs_run;
    }
    return rs_run;
}

// Phase B with FUSED reciprocal: one MUFU serves both ds and dt:
//   p = 1 - rs[l+1]*r[l]; q = 1 - rt[l-1]*r[l]
//   x = 1/(p*q);  ds = x*q;  dt = x*p;
__device__ __forceinline__ void compB(BState& st, const BufB& Bu, int l0,
                                      float* sh, int tx, unsigned base,
                                      float* fd, float* ab) {
    float rsv[4];
    #pragma unroll
    for (int k = 0; k < 4; ++k)
        rsv[k] = sh[(l0 + k + 1) * BLOCK + tx];   // rs[l+1]
    #pragma unroll
    for (int k = 0; k < 4; ++k) {
        unsigned idx = base + (unsigned)(l0 + k) * CCH;
        float s_down = st.ds_prev * (st.s_prev + Bu.sv[k] * st.r_prev);
        float G = st.F + s_down;
        __stcs(&fd[idx], G);

        float p = 1.0f - rsv[k] * Bu.rv[k];
        float q = 1.0f - st.rt_run * Bu.rv[k];
        float x = frcp(p * q);                      // single MUFU
        float dsl = x * q;                          // ds[l]
        float dtl = x * p;                          // dt[l]

        float td = Bu.tv[k] * dsl;
        ab[idx] = Bu.av[k] * (1.0f + rsv[k] * td) * G; // re-read in C
        st.F = G * td;
        st.ds_prev = dsl;

        st.rt_run = Bu.rv[k] + st.rt_run * Bu.tv[k] * Bu.tv[k] * dtl;
        sh[(l0 + k) * BLOCK + tx] = st.rt_run;         // overwrite dead rs

        st.s_prev = Bu.sv[k];
        st.r_prev = Bu.rv[k];
    }
}

// Phase C with pairwise-FUSED reciprocals: 2 MUFUs serve 4 dt's.
__device__ __forceinline__ void compC(CState& st, const BufC& Bu, int m0,
                                      float* sh, int tx, unsigned base,
                                      float* fu, float* ab) {
    float rtv[4], qv[4], dtv[4];
    #pragma unroll
    for (int k = 0; k < 4; ++k)
        rtv[k] = sh[(m0 - 2 - k) * BLOCK + tx];   // rt[m-2]
    #pragma unroll
    for (int k = 0; k < 4; ++k)
        qv[k] = 1.0f - rtv[k] * Bu.rv[k];
    {
        float x01 = frcp(qv[0] * qv[1]);
        float x23 = frcp(qv[2] * qv[3]);
        dtv[0] = x01 * qv[1];
        dtv[1] = x01 * qv[0];
        dtv[2] = x23 * qv[3];
        dtv[3] = x23 * qv[2];
    }
    #pragma unroll
    for (int k = 0; k < 4; ++k) {
        int mm = m0 - k;
        float dt_m1 = dtv[k];                           // dt[mm-1]
        float s_up = st.dt_m * (st.s_m + Bu.sv[k] * st.r_m);
        float G = st.Fu + s_up;
        __stcs(&fu[base + (unsigned)mm * CCH], G);

        float tdm1 = Bu.tv[k] * dt_m1;
        float au = G * Bu.av[k] * (1.0f + rtv[k] * tdm1);
        __stcs(&ab[base + (unsigned)(mm - 1) * CCH], Bu.abv[k] + au);
        st.Fu = G * tdm1;

        st.s_m = Bu.sv[k];
        st.r_m = Bu.rv[k];
        st.dt_m = dt_m1;
    }
}

__global__ __launch_bounds__(BLOCK, 10)   // 10 blocks/SM -> reg cap 102
void adding_doubling_kernel(const float* __restrict__ a,
                            const float* __restrict__ r,
                            const float* __restrict__ t,
                            const float* __restrict__ s,
                            float* __restrict__ out)
{
    extern __shared__ float smem[];
    const int tx = threadIdx.x;

    const unsigned tid = blockIdx.x * BLOCK + tx;
    const unsigned base = (tid >> 7) * (NL * CCH) + (tid & (CCH - 1));
    const unsigned BNC  = BCOL * NL * CCH;

    float* fd = out;            // flux_down
    float* fu = out + BNC;      // flux_up
    float* ab = out + 2u * BNC; // absorbed

#define SH_R(l) smem[(l) * BLOCK + tx]

    BufB B0, B1;   // phase-B buffers (B0 pre-loaded during phase A tail)

    // ---------------- Phase A: bottom-up cumulative surface reflection ----
    // ROLLED pipeline: batches l0 = 58,54,...,6 (l=58..3), tail l=2,1
    {
        float rs_run = r[base + (NL - 1) * CCH];
        SH_R(NL - 1) = rs_run;

        BufA A0, A1;
        int l = NL - 2;                       // 58
        loadA(A0, r, t, base, l);
        #pragma unroll 1
        for (int it = 0; it < 6; ++it, l -= 8) {
            loadA(A1, r, t, base, l - 4);
            rs_run = compA(rs_run, A0, l, smem, tx);
            loadA(A0, r, t, base, l - 8);
            rs_run = compA(rs_run, A1, l - 4, smem, tx);
        }
        // l == 10; A0 holds batch 10
        loadA(A1, r, t, base, 6);
        rs_run = compA(rs_run, A0, 10, smem, tx);
        loadB(B0, s, r, t, a, base, 1);       // hide phase-B cold start
        rs_run = compA(rs_run, A1, 6, smem, tx);

        #pragma unroll
        for (int l2 = 2; l2 >= 1; --l2) {     // tail
            unsigned idx = base + (unsigned)l2 * CCH;
            float rl = r[idx], tl = t[idx];
            float dd = frcp(1.0f - rs_run * rl);
            rs_run = rl + rs_run * tl * tl * dd;
            SH_R(l2) = rs_run;
        }
    }

    BufC C0, C1;   // phase-C buffers (C0 inputs pre-loaded in phase B tail)

    // ---------------- Phase B: forward — down flux + top-down rt ----------
    // ROLLED pipeline: batches l0 = 1,5,...,53 (l=1..56), tail l=57..59
    {
        BState st;
        st.s_prev = s[base];
        st.r_prev = r[base];
        float rs1 = SH_R(1);
        st.ds_prev = frcp(1.0f - rs1 * st.r_prev);   // ds[0]
        st.rt_run = st.r_prev;                        // rt[0]
        SH_R(0) = st.rt_run;
        __stcs(&fd[base], 0.0f);
        st.F = 0.0f;

        int l = 1;
        #pragma unroll 1
        for (int it = 0; it < 6; ++it, l += 8) {
            loadB(B1, s, r, t, a, base, l + 4);
            compB(st, B0, l, smem, tx, base, fd, ab);
            loadB(B0, s, r, t, a, base, l + 8);
            compB(st, B1, l + 4, smem, tx, base, fd, ab);
        }
        // l == 49; B0 holds batch 49
        loadB(B1, s, r, t, a, base, 53);
        compB(st, B0, 49, smem, tx, base, fd, ab);
        loadCin(C0, s, r, t, a, base, 59);    // SAFE hoist: pure inputs only
        compB(st, B1, 53, smem, tx, base, fd, ab);

        #pragma unroll
        for (int l2 = 57; l2 < NL; ++l2) {    // tail l = 57, 58, 59
            unsigned idx = base + (unsigned)l2 * CCH;
            float sl = s[idx], rl = r[idx], tl = t[idx], al = a[idx];

            float s_down = st.ds_prev * (st.s_prev + sl * st.r_prev);
            float G = st.F + s_down;
            __stcs(&fd[idx], G);

            float absd;
            if (l2 < NL - 1) {
                float rsl1 = SH_R(l2 + 1);
                float dsl  = frcp(1.0f - rsl1 * rl);
                float td = tl * dsl;
                absd = al * (1.0f + rsl1 * td) * G;
                st.F = G * td;
                st.ds_prev = dsl;
            } else {
                absd = al * G;
            }
            ab[idx] = absd;

            float dd = frcp(1.0f - st.rt_run * rl);
            st.rt_run = rl + st.rt_run * tl * tl * dd;
            SH_R(l2) = st.rt_run;

            st.s_prev = sl;
            st.r_prev = rl;
        }
    }

    // ---------------- Phase C: reverse — up flux ---------------------------
    // ROLLED pipeline: batches m0 = 59,55,...,7 (m=59..4), tail m=3,2, epi.
    {
        // ab[55..58] were written by this same thread in phase B above;
        // load here (after the writes) — program-order correct, L1/L2 hit.
        loadCab(C0, ab, base, 59);

        CState st;
        st.Fu = 0.0f;
        unsigned idxN = base + (NL - 1) * CCH;
        st.s_m = __ldcs(&s[idxN]);
        st.r_m = __ldcs(&r[idxN]);
        st.dt_m = frcp(1.0f - SH_R(NL - 2) * st.r_m);   // dt[N-1]

        int m = NL - 1;                        // 59
        #pragma unroll 1
        for (int it = 0; it < 6; ++it, m -= 8) {
            loadC(C1, s, r, t, a, ab, base, m - 4);
            compC(st, C0, m, smem, tx, base, fu, ab);
            loadC(C0, s, r, t, a, ab, base, m - 8);
            compC(st, C1, m - 4, smem, tx, base, fu, ab);
        }
        // m == 11; C0 holds batch 11
        loadC(C1, s, r, t, a, ab, base, 7);
        compC(st, C0, 11, smem, tx, base, fu, ab);
        compC(st, C1, 7, smem, tx, base, fu, ab);

        #pragma unroll
        for (int m2 = 3; m2 >= 2; --m2) {      // tail m = 3, 2
            unsigned idxm1 = base + (unsigned)(m2 - 1) * CCH;
            float s_m1 = __ldcs(&s[idxm1]);
            float r_m1 = __ldcs(&r[idxm1]);
            float t_m1 = __ldcs(&t[idxm1]);
            float a_m1 = __ldcs(&a[idxm1]);
            float ab_old = __ldcs(&ab[idxm1]);

            float rt_m2 = SH_R(m2 - 2);
            float dt_m1 = frcp(1.0f - rt_m2 * r_m1);

            float s_up_m = st.dt_m * (st.s_m + s_m1 * st.r_m);
            float G = st.Fu + s_up_m;
            __stcs(&fu[base + (unsigned)m2 * CCH], G);

            float tdm1 = t_m1 * dt_m1;
            float au = G * a_m1 * (1.0f + rt_m2 * tdm1);
            __stcs(&ab[idxm1], ab_old + au);
            st.Fu = G * tdm1;

            st.s_m = s_m1;
            st.r_m = r_m1;
            st.dt_m = dt_m1;
        }

        // m = 1 and m = 0 epilogue; state: s_m=s[1], r_m=r[1], dt_m=dt[1]
        float s0 = __ldcs(&s[base]);
        float t0 = __ldcs(&t[base]);
        float a0 = __ldcs(&a[base]);
        float s_up1 = st.dt_m * (st.s_m + s0 * st.r_m);
        float flux1 = st.Fu + s_up1;
        __stcs(&fu[base + CCH], flux1);           // flux_up[1]
        __stcs(&ab[base], flux1 * a0);            // absorbed[0] (down = 0)
        __stcs(&fu[base], flux1 * t0 + s0);       // flux_up[0]
    }

#undef SH_R
}

extern "C" void kernel_launch(void* const* d_in, const int* in_sizes, int n_in,
                              void* d_out, int out_size)
{
    const float* a = (const float*)d_in[0];
    const float* r = (const float*)d_in[1];
    const float* t = (const float*)d_in[2];
    const float* s = (const float*)d_in[3];
    float* out = (float*)d_out;

    cudaFuncSetAttribute(adding_doubling_kernel,
                         cudaFuncAttributeMaxDynamicSharedMemorySize,
                         (int)SMEM_BYTES);

    const int total = BCOL * CCH;                 // 262144 threads
    const int grid = total / BLOCK;               // 4096 blocks
    adding_doubling_kernel<<<grid, BLOCK, SMEM_BYTES>>>(a, r, t, s, out);
}

// round 15
// speedup vs baseline: 1.2119x; 1.1206x over previous
#include <cuda_runtime.h>

// Problem constants (from reference: B=2048, N=60, C=128)
#define BCOL 2048
#define NL   60
#define CCH  128
#define BLOCK 128

// dynamic smem: ONE per-thread array of NL floats, [layer][thread].
// Holds rs[] (phase A), progressively overwritten by rt[] (phase B).
// NO pad: residency is register-limited to 5 blocks/SM (96 regs), so the
// old 36 KB pad only shrank the L1D carveout. 30 KB x 5 = 150 KB smem/SM.
#define SMEM_BYTES  (NL * BLOCK * sizeof(float))

__device__ __forceinline__ float frcp(float x) {
    return __fdividef(1.0f, x);     // MUFU.RCP path, ~2ulp
}

struct BufA { float rv[4], tv[4]; };
struct BufB { float sv[4], rv[4], tv[4], av[4]; };
struct BufC { float sv[4], rv[4], tv[4], av[4], abv[4]; };

struct BState { float s_prev, r_prev, ds_prev, rt_run, F; };
struct CState { float Fu, s_m, r_m, dt_m; };

// ---- load helpers: issue all batch loads back-to-back (max MLP) ----
__device__ __forceinline__ void loadA(BufA& B, const float* __restrict__ r,
                                      const float* __restrict__ t,
                                      unsigned base, int l0) {
    #pragma unroll
    for (int k = 0; k < 4; ++k) {
        unsigned idx = base + (unsigned)(l0 - k) * CCH;
        B.rv[k] = r[idx];
        B.tv[k] = t[idx];
    }
}
__device__ __forceinline__ void loadB(BufB& B, const float* __restrict__ s,
                                      const float* __restrict__ r,
                                      const float* __restrict__ t,
                                      const float* __restrict__ a,
                                      unsigned base, int l0) {
    #pragma unroll
    for (int k = 0; k < 4; ++k) {
        unsigned idx = base + (unsigned)(l0 + k) * CCH;
        B.sv[k] = s[idx];
        B.rv[k] = r[idx];
        B.tv[k] = t[idx];
        B.av[k] = a[idx];
    }
}
// pure-input part of a phase-C batch: SAFE to hoist before phase-B writes
__device__ __forceinline__ void loadCin(BufC& B, const float* __restrict__ s,
                                        const float* __restrict__ r,
                                        const float* __restrict__ t,
                                        const float* __restrict__ a,
                                        unsigned base, int m0) {
    #pragma unroll
    for (int k = 0; k < 4; ++k) {
        unsigned idx = base + (unsigned)(m0 - 1 - k) * CCH;
        B.sv[k]  = __ldcs(&s[idx]);   // last use of inputs
        B.rv[k]  = __ldcs(&r[idx]);
        B.tv[k]  = __ldcs(&t[idx]);
        B.av[k]  = __ldcs(&a[idx]);
    }
}
// absorbed_down part: MUST issue after phase B wrote ab for these layers
__device__ __forceinline__ void loadCab(BufC& B, const float* __restrict__ ab,
                                        unsigned base, int m0) {
    #pragma unroll
    for (int k = 0; k < 4; ++k) {
        unsigned idx = base + (unsigned)(m0 - 1 - k) * CCH;
        B.abv[k] = __ldcs(&ab[idx]);  // read once, then overwritten
    }
}
__device__ __forceinline__ void loadC(BufC& B, const float* __restrict__ s,
                                      const float* __restrict__ r,
                                      const float* __restrict__ t,
                                      const float* __restrict__ a,
                                      const float* __restrict__ ab,
                                      unsigned base, int m0) {
    loadCin(B, s, r, t, a, base, m0);
    loadCab(B, ab, base, m0);
}

// ---- compute helpers (math identical to R12) ----
__device__ __forceinline__ float compA(float rs_run, const BufA& B, int l0,
                                       float* sh, int tx) {
    #pragma unroll
    for (int k = 0; k < 4; ++k) {
        float dd = frcp(1.0f - rs_run * B.rv[k]);
        rs_run = B.rv[k] + rs_run * B.tv[k] * B.tv[k] * dd;
        sh[(l0 - k) * BLOCK + tx] = rs_run;
    }
    return rs_run;
}

// Phase B with FUSED reciprocal: one MUFU serves both ds and dt:
//   p = 1 - rs[l+1]*r[l]; q = 1 - rt[l-1]*r[l]
//   x = 1/(p*q);  ds = x*q;  dt = x*p;
__device__ __forceinline__ void compB(BState& st, const BufB& Bu, int l0,
                                      float* sh, int tx, unsigned base,
                                      float* fd, float* ab) {
    float rsv[4];
    #pragma unroll
    for (int k = 0; k < 4; ++k)
        rsv[k] = sh[(l0 + k + 1) * BLOCK + tx];   // rs[l+1]
    #pragma unroll
    for (int k = 0; k < 4; ++k) {
        unsigned idx = base + (unsigned)(l0 + k) * CCH;
        float s_down = st.ds_prev * (st.s_prev + Bu.sv[k] * st.r_prev);
        float G = st.F + s_down;
        __stcs(&fd[idx], G);

        float p = 1.0f - rsv[k] * Bu.rv[k];
        float q = 1.0f - st.rt_run * Bu.rv[k];
        float x = frcp(p * q);                      // single MUFU
        float dsl = x * q;                          // ds[l]
        float dtl = x * p;                          // dt[l]

        float td = Bu.tv[k] * dsl;
        ab[idx] = Bu.av[k] * (1.0f + rsv[k] * td) * G; // re-read in C
        st.F = G * td;
        st.ds_prev = dsl;

        st.rt_run = Bu.rv[k] + st.rt_run * Bu.tv[k] * Bu.tv[k] * dtl;
        sh[(l0 + k) * BLOCK + tx] = st.rt_run;         // overwrite dead rs

        st.s_prev = Bu.sv[k];
        st.r_prev = Bu.rv[k];
    }
}

// Phase C with pairwise-FUSED reciprocals: 2 MUFUs serve 4 dt's.
__device__ __forceinline__ void compC(CState& st, const BufC& Bu, int m0,
                                      float* sh, int tx, unsigned base,
                                      float* fu, float* ab) {
    float rtv[4], qv[4], dtv[4];
    #pragma unroll
    for (int k = 0; k < 4; ++k)
        rtv[k] = sh[(m0 - 2 - k) * BLOCK + tx];   // rt[m-2]
    #pragma unroll
    for (int k = 0; k < 4; ++k)
        qv[k] = 1.0f - rtv[k] * Bu.rv[k];
    {
        float x01 = frcp(qv[0] * qv[1]);
        float x23 = frcp(qv[2] * qv[3]);
        dtv[0] = x01 * qv[1];
        dtv[1] = x01 * qv[0];
        dtv[2] = x23 * qv[3];
        dtv[3] = x23 * qv[2];
    }
    #pragma unroll
    for (int k = 0; k < 4; ++k) {
        int mm = m0 - k;
        float dt_m1 = dtv[k];                           // dt[mm-1]
        float s_up = st.dt_m * (st.s_m + Bu.sv[k] * st.r_m);
        float G = st.Fu + s_up;
        __stcs(&fu[base + (unsigned)mm * CCH], G);

        float tdm1 = Bu.tv[k] * dt_m1;
        float au = G * Bu.av[k] * (1.0f + rtv[k] * tdm1);
        __stcs(&ab[base + (unsigned)(mm - 1) * CCH], Bu.abv[k] + au);
        st.Fu = G * tdm1;

        st.s_m = Bu.sv[k];
        st.r_m = Bu.rv[k];
        st.dt_m = dt_m1;
    }
}

__global__ __launch_bounds__(BLOCK, 5)   // 5 blocks/SM, reg cap 102
void adding_doubling_kernel(const float* __restrict__ a,
                            const float* __restrict__ r,
                            const float* __restrict__ t,
                            const float* __restrict__ s,
                            float* __restrict__ out)
{
    extern __shared__ float smem[];
    const int tx = threadIdx.x;

    const unsigned tid = blockIdx.x * BLOCK + tx;
    const unsigned base = (tid >> 7) * (NL * CCH) + (tid & (CCH - 1));
    const unsigned BNC  = BCOL * NL * CCH;

    float* fd = out;            // flux_down
    float* fu = out + BNC;      // flux_up
    float* ab = out + 2u * BNC; // absorbed

#define SH_R(l) smem[(l) * BLOCK + tx]

    BufB B0, B1;   // phase-B buffers (B0 pre-loaded during phase A tail)

    // ---------------- Phase A: bottom-up cumulative surface reflection ----
    // Pipeline (2x-unrolled window): batches l0 = 58,54,...,6; tail l=2,1
    {
        float rs_run = r[base + (NL - 1) * CCH];
        SH_R(NL - 1) = rs_run;

        BufA A0, A1;
        int l = NL - 2;                       // 58
        loadA(A0, r, t, base, l);
        #pragma unroll 2
        for (int it = 0; it < 6; ++it, l -= 8) {
            loadA(A1, r, t, base, l - 4);
            rs_run = compA(rs_run, A0, l, smem, tx);
            loadA(A0, r, t, base, l - 8);
            rs_run = compA(rs_run, A1, l - 4, smem, tx);
        }
        // l == 10; A0 holds batch 10
        loadA(A1, r, t, base, 6);
        rs_run = compA(rs_run, A0, 10, smem, tx);
        loadB(B0, s, r, t, a, base, 1);       // hide phase-B cold start
        rs_run = compA(rs_run, A1, 6, smem, tx);

        #pragma unroll
        for (int l2 = 2; l2 >= 1; --l2) {     // tail
            unsigned idx = base + (unsigned)l2 * CCH;
            float rl = r[idx], tl = t[idx];
            float dd = frcp(1.0f - rs_run * rl);
            rs_run = rl + rs_run * tl * tl * dd;
            SH_R(l2) = rs_run;
        }
    }

    BufC C0, C1;   // phase-C buffers (C0 inputs pre-loaded in phase B tail)

    // ---------------- Phase B: forward — down flux + top-down rt ----------
    // Pipeline (2x-unrolled window): batches l0 = 1,5,...,53; tail l=57..59
    {
        BState st;
        st.s_prev = s[base];
        st.r_prev = r[base];
        float rs1 = SH_R(1);
        st.ds_prev = frcp(1.0f - rs1 * st.r_prev);   // ds[0]
        st.rt_run = st.r_prev;                        // rt[0]
        SH_R(0) = st.rt_run;
        __stcs(&fd[base], 0.0f);
        st.F = 0.0f;

        int l = 1;
        #pragma unroll 2
        for (int it = 0; it < 6; ++it, l += 8) {
            loadB(B1, s, r, t, a, base, l + 4);
            compB(st, B0, l, smem, tx, base, fd, ab);
            loadB(B0, s, r, t, a, base, l + 8);
            compB(st, B1, l + 4, smem, tx, base, fd, ab);
        }
        // l == 49; B0 holds batch 49
        loadB(B1, s, r, t, a, base, 53);
        compB(st, B0, 49, smem, tx, base, fd, ab);
        loadCin(C0, s, r, t, a, base, 59);    // SAFE hoist: pure inputs only
        compB(st, B1, 53, smem, tx, base, fd, ab);

        #pragma unroll
        for (int l2 = 57; l2 < NL; ++l2) {    // tail l = 57, 58, 59
            unsigned idx = base + (unsigned)l2 * CCH;
            float sl = s[idx], rl = r[idx], tl = t[idx], al = a[idx];

            float s_down = st.ds_prev * (st.s_prev + sl * st.r_prev);
            float G = st.F + s_down;
            __stcs(&fd[idx], G);

            float absd;
            if (l2 < NL - 1) {
                float rsl1 = SH_R(l2 + 1);
                float dsl  = frcp(1.0f - rsl1 * rl);
                float td = tl * dsl;
                absd = al * (1.0f + rsl1 * td) * G;
                st.F = G * td;
                st.ds_prev = dsl;
            } else {
                absd = al * G;
            }
            ab[idx] = absd;

            float dd = frcp(1.0f - st.rt_run * rl);
            st.rt_run = rl + st.rt_run * tl * tl * dd;
            SH_R(l2) = st.rt_run;

            st.s_prev = sl;
            st.r_prev = rl;
        }
    }

    // ---------------- Phase C: reverse — up flux ---------------------------
    // Pipeline (2x-unrolled window): batches m0 = 59,55,...,7; tail m=3,2
    {
        // ab[55..58] were written by this same thread in phase B above;
        // load here (after the writes) — program-order correct, L1/L2 hit.
        loadCab(C0, ab, base, 59);

        CState st;
        st.Fu = 0.0f;
        unsigned idxN = base + (NL - 1) * CCH;
        st.s_m = __ldcs(&s[idxN]);
        st.r_m = __ldcs(&r[idxN]);
        st.dt_m = frcp(1.0f - SH_R(NL - 2) * st.r_m);   // dt[N-1]

        int m = NL - 1;                        // 59
        #pragma unroll 2
        for (int it = 0; it < 6; ++it, m -= 8) {
            loadC(C1, s, r, t, a, ab, base, m - 4);
            compC(st, C0, m, smem, tx, base, fu, ab);
            loadC(C0, s, r, t, a, ab, base, m - 8);
            compC(st, C1, m - 4, smem, tx, base, fu, ab);
        }
        // m == 11; C0 holds batch 11
        loadC(C1, s, r, t, a, ab, base, 7);
        compC(st, C0, 11, smem, tx, base, fu, ab);
        compC(st, C1, 7, smem, tx, base, fu, ab);

        #pragma unroll
        for (int m2 = 3; m2 >= 2; --m2) {      // tail m = 3, 2
            unsigned idxm1 = base + (unsigned)(m2 - 1) * CCH;
            float s_m1 = __ldcs(&s[idxm1]);
            float r_m1 = __ldcs(&r[idxm1]);
            float t_m1 = __ldcs(&t[idxm1]);
            float a_m1 = __ldcs(&a[idxm1]);
            float ab_old = __ldcs(&ab[idxm1]);

            float rt_m2 = SH_R(m2 - 2);
            float dt_m1 = frcp(1.0f - rt_m2 * r_m1);

            float s_up_m = st.dt_m * (st.s_m + s_m1 * st.r_m);
            float G = st.Fu + s_up_m;
            __stcs(&fu[base + (unsigned)m2 * CCH], G);

            float tdm1 = t_m1 * dt_m1;
            float au = G * a_m1 * (1.0f + rt_m2 * tdm1);
            __stcs(&ab[idxm1], ab_old + au);
            st.Fu = G * tdm1;

            st.s_m = s_m1;
            st.r_m = r_m1;
            st.dt_m = dt_m1;
        }

        // m = 1 and m = 0 epilogue; state: s_m=s[1], r_m=r[1], dt_m=dt[1]
        float s0 = __ldcs(&s[base]);
        float t0 = __ldcs(&t[base]);
        float a0 = __ldcs(&a[base]);
        float s_up1 = st.dt_m * (st.s_m + s0 * st.r_m);
        float flux1 = st.Fu + s_up1;
        __stcs(&fu[base + CCH], flux1);           // flux_up[1]
        __stcs(&ab[base], flux1 * a0);            // absorbed[0] (down = 0)
        __stcs(&fu[base], flux1 * t0 + s0);       // flux_up[0]
    }

#undef SH_R
}

extern "C" void kernel_launch(void* const* d_in, const int* in_sizes, int n_in,
                              void* d_out, int out_size)
{
    const float* a = (const float*)d_in[0];
    const float* r = (const float*)d_in[1];
    const float* t = (const float*)d_in[2];
    const float* s = (const float*)d_in[3];
    float* out = (float*)d_out;

    cudaFuncSetAttribute(adding_doubling_kernel,
                         cudaFuncAttributeMaxDynamicSharedMemorySize,
                         (int)SMEM_BYTES);

    const int total = BCOL * CCH;                 // 262144 threads
    const int grid = (total + BLOCK - 1) / BLOCK; // 2048 blocks
    adding_doubling_kernel<<<grid, BLOCK, SMEM_BYTES>>>(a, r, t, s, out);
}